// round 3
// baseline (speedup 1.0000x reference)
#include <cuda_runtime.h>
#include <cuda_bf16.h>
#include <math.h>

#define Bdim 16
#define Tdim 24
#define Ndim 512
#define Ddim 64
#define Hdim 4
#define HD   16
#define Fdim 256
#define MTOK (Bdim*Tdim*Ndim)   // 196608
#define EPS  1e-5f

// ---------------- scratch (referenced ONLY from device code) ----------------
__device__ float d_q[MTOK*Ddim];
__device__ float d_k[MTOK*Ddim];
__device__ float d_v[MTOK*Ddim];
__device__ float d_att[MTOK*Ddim];
__device__ float d_h[MTOK*Ddim];
__device__ float d_p1[MTOK*Ddim];
__device__ float d_p2[MTOK*Ddim];
__device__ float d_h2[MTOK*Ddim];
__device__ float d_Ahat[Ndim*Ndim];
__device__ float d_dinv[Ndim];

// ---------------- helpers ----------------
__device__ __forceinline__ float reduce64(float v, float* red, int tx) {
    if (tx < 64) red[tx] = v;
    __syncthreads();
#pragma unroll
    for (int s = 32; s > 0; s >>= 1) {
        if (tx < s) red[tx] += red[tx + s];
        __syncthreads();
    }
    float r = red[0];
    __syncthreads();
    return r;
}

// ---------------- degree / Ahat ----------------
__global__ void deg_kernel(const float* __restrict__ adj) {
    int m = blockIdx.x, tx = threadIdx.x;
    float s = 0.f;
    for (int n = tx; n < Ndim; n += 256) s += adj[m*Ndim + n];
    __shared__ float red[256];
    red[tx] = s; __syncthreads();
#pragma unroll
    for (int st = 128; st > 0; st >>= 1) {
        if (tx < st) red[tx] += red[tx + st];
        __syncthreads();
    }
    if (tx == 0) d_dinv[m] = rsqrtf(fmaxf(red[0] + 1.0f, 1e-12f));
}

__global__ void ahat_kernel(const float* __restrict__ adj) {
    int m = blockIdx.x, n = threadIdx.x;  // 512 threads
    float a = adj[m*Ndim + n] + (m == n ? 1.0f : 0.0f);
    d_Ahat[m*Ndim + n] = d_dinv[m] * a * d_dinv[n];
}

// ---------------- fused QKV: loads x tile once, writes d_q/d_k/d_v ----------------
__global__ void qkv_gemm(const float* __restrict__ x,
                         const float* __restrict__ Wq, const float* __restrict__ bq,
                         const float* __restrict__ Wk, const float* __restrict__ bk,
                         const float* __restrict__ Wv, const float* __restrict__ bv) {
    __shared__ float As[64][65];
    __shared__ float Ws[64][65];
    int tx = threadIdx.x;
    size_t mbase = (size_t)blockIdx.x * 64;
#pragma unroll 4
    for (int i = tx; i < 4096; i += 256) {
        int r = i >> 6, c = i & 63;
        As[r][c] = x[(mbase + r)*64 + c];
    }
    int r0 = (tx >> 4) * 4, c0 = (tx & 15) * 4;
    const float* Wm[3] = {Wq, Wk, Wv};
    const float* bm[3] = {bq, bk, bv};
    float* Om[3] = {d_q, d_k, d_v};   // device-side symbol references: valid
#pragma unroll
    for (int m = 0; m < 3; m++) {
        __syncthreads();   // As ready (m=0) / previous readers of Ws done (m>0)
        const float* W = Wm[m];
#pragma unroll 4
        for (int i = tx; i < 4096; i += 256) {
            int r = i >> 6, c = i & 63;
            Ws[r][c] = W[r*64 + c];
        }
        __syncthreads();
        float acc[4][4] = {};
#pragma unroll
        for (int kk = 0; kk < 64; kk++) {
            float a0 = As[r0+0][kk], a1 = As[r0+1][kk], a2 = As[r0+2][kk], a3 = As[r0+3][kk];
            float w0 = Ws[kk][c0+0], w1 = Ws[kk][c0+1], w2 = Ws[kk][c0+2], w3 = Ws[kk][c0+3];
            acc[0][0] += a0*w0; acc[0][1] += a0*w1; acc[0][2] += a0*w2; acc[0][3] += a0*w3;
            acc[1][0] += a1*w0; acc[1][1] += a1*w1; acc[1][2] += a1*w2; acc[1][3] += a1*w3;
            acc[2][0] += a2*w0; acc[2][1] += a2*w1; acc[2][2] += a2*w2; acc[2][3] += a2*w3;
            acc[3][0] += a3*w0; acc[3][1] += a3*w1; acc[3][2] += a3*w2; acc[3][3] += a3*w3;
        }
        float* O = Om[m];
        const float* bias = bm[m];
#pragma unroll
        for (int i = 0; i < 4; i++)
#pragma unroll
            for (int j = 0; j < 4; j++)
                O[(mbase + r0 + i)*64 + c0 + j] = acc[i][j] + bias[c0 + j];
    }
}

// ---------------- temporal attention: one block per (b, n) ----------------
__global__ void attn_kernel() {
    int bn = blockIdx.x;
    int b = bn / Ndim, n = bn % Ndim;
    __shared__ float qs[Tdim][Ddim], ks[Tdim][Ddim], vs[Tdim][Ddim];
    __shared__ float sc[Hdim][Tdim][Tdim];
    int tx = threadIdx.x;  // 256
    for (int i = tx; i < Tdim*Ddim; i += 256) {
        int t = i / Ddim, d = i % Ddim;
        size_t off = (((size_t)b*Tdim + t)*Ndim + n)*Ddim + d;
        qs[t][d] = d_q[off]; ks[t][d] = d_k[off]; vs[t][d] = d_v[off];
    }
    __syncthreads();
    for (int i = tx; i < Hdim*Tdim*Tdim; i += 256) {
        int h = i / (Tdim*Tdim), r = i % (Tdim*Tdim);
        int tq = r / Tdim, tk = r % Tdim;
        float s = 0.f;
#pragma unroll
        for (int d = 0; d < HD; d++) s += qs[tq][h*HD + d] * ks[tk][h*HD + d];
        sc[h][tq][tk] = s * 0.25f;   // hd^-0.5
    }
    __syncthreads();
    if (tx < Hdim*Tdim) {
        int h = tx / Tdim, tq = tx % Tdim;
        float m = -1e30f;
#pragma unroll
        for (int tk = 0; tk < Tdim; tk++) m = fmaxf(m, sc[h][tq][tk]);
        float sum = 0.f;
#pragma unroll
        for (int tk = 0; tk < Tdim; tk++) {
            float e = __expf(sc[h][tq][tk] - m);
            sc[h][tq][tk] = e; sum += e;
        }
        float inv = 1.0f / sum;
#pragma unroll
        for (int tk = 0; tk < Tdim; tk++) sc[h][tq][tk] *= inv;
    }
    __syncthreads();
    for (int i = tx; i < Tdim*Ddim; i += 256) {
        int tq = i / Ddim, d = i % Ddim;
        int h = d / HD;
        float o = 0.f;
#pragma unroll
        for (int tk = 0; tk < Tdim; tk++) o += sc[h][tq][tk] * vs[tk][d];
        d_att[(((size_t)b*Tdim + tq)*Ndim + n)*Ddim + d] = o;
    }
}

// ---------------- O-proj + residual + LN -> d_h ----------------
__global__ void oproj_ln(const float* __restrict__ x,
                         const float* __restrict__ Wo, const float* __restrict__ bo,
                         const float* __restrict__ g, const float* __restrict__ bb) {
    size_t tok = blockIdx.x;
    int d = threadIdx.x;  // 64
    __shared__ float row[64];
    __shared__ float red[64];
    row[d] = d_att[tok*64 + d];
    __syncthreads();
    float y = bo[d];
#pragma unroll
    for (int i = 0; i < 64; i++) y += row[i] * Wo[i*64 + d];
    y += x[tok*64 + d];
    float mean = reduce64(y, red, d) * (1.0f/64.f);
    float c = y - mean;
    float var = reduce64(c*c, red, d) * (1.0f/64.f);
    d_h[tok*64 + d] = c * rsqrtf(var + EPS) * g[d] + bb[d];
}

// ---------------- graph GEMM: stage 0: p1 = Ahat@h ; stage 1: p2 = Ahat@p1 ----------------
__global__ void graph_gemm(int stage) {
    const float* __restrict__ Hin = stage ? (const float*)d_p1 : (const float*)d_h;
    float* __restrict__ Hout      = stage ? d_p2 : d_p1;
    __shared__ float As[64][65];
    __shared__ float Bs[64][65];
    int tx = threadIdx.x;
    int mbase = blockIdx.x * 64;                      // node tile (8 tiles)
    size_t hbase = (size_t)blockIdx.y * Ndim * Ddim;  // bt batch
    int r0 = (tx >> 4) * 4, c0 = (tx & 15) * 4;
    float acc[4][4] = {};
    for (int kt = 0; kt < 8; kt++) {
#pragma unroll 4
        for (int i = tx; i < 4096; i += 256) {
            int r = i >> 6, c = i & 63;
            As[r][c] = d_Ahat[(size_t)(mbase + r)*Ndim + kt*64 + c];
            Bs[r][c] = Hin[hbase + (size_t)(kt*64 + r)*64 + c];
        }
        __syncthreads();
#pragma unroll
        for (int kk = 0; kk < 64; kk++) {
            float a0 = As[r0+0][kk], a1 = As[r0+1][kk], a2 = As[r0+2][kk], a3 = As[r0+3][kk];
            float w0 = Bs[kk][c0+0], w1 = Bs[kk][c0+1], w2 = Bs[kk][c0+2], w3 = Bs[kk][c0+3];
            acc[0][0] += a0*w0; acc[0][1] += a0*w1; acc[0][2] += a0*w2; acc[0][3] += a0*w3;
            acc[1][0] += a1*w0; acc[1][1] += a1*w1; acc[1][2] += a1*w2; acc[1][3] += a1*w3;
            acc[2][0] += a2*w0; acc[2][1] += a2*w1; acc[2][2] += a2*w2; acc[2][3] += a2*w3;
            acc[3][0] += a3*w0; acc[3][1] += a3*w1; acc[3][2] += a3*w2; acc[3][3] += a3*w3;
        }
        __syncthreads();
    }
#pragma unroll
    for (int i = 0; i < 4; i++)
#pragma unroll
        for (int j = 0; j < 4; j++)
            Hout[hbase + (size_t)(mbase + r0 + i)*64 + c0 + j] = acc[i][j];
}

// ---------------- gc combine + residual + LN -> d_h2 ----------------
__global__ void gcomb_ln(const float* __restrict__ gcW, const float* __restrict__ gcb,
                         const float* __restrict__ g, const float* __restrict__ bb) {
    size_t tok = blockIdx.x;
    int d = threadIdx.x;  // 64
    __shared__ float hr[64], r1[64], r2[64];
    __shared__ float red[64];
    hr[d] = d_h[tok*64 + d];
    r1[d] = d_p1[tok*64 + d];
    r2[d] = d_p2[tok*64 + d];
    __syncthreads();
    float y = gcb[0*64 + d] + gcb[1*64 + d] + gcb[2*64 + d];
#pragma unroll
    for (int i = 0; i < 64; i++) {
        y += hr[i] * gcW[0*4096 + i*64 + d];
        y += r1[i] * gcW[1*4096 + i*64 + d];
        y += r2[i] * gcW[2*4096 + i*64 + d];
    }
    y += hr[d];
    float mean = reduce64(y, red, d) * (1.0f/64.f);
    float c = y - mean;
    float var = reduce64(c*c, red, d) * (1.0f/64.f);
    d_h2[tok*64 + d] = c * rsqrtf(var + EPS) * g[d] + bb[d];
}

// ---------------- FFN + residual + LN -> out ----------------
__global__ void ffn_ln(const float* __restrict__ W1, const float* __restrict__ b1,
                       const float* __restrict__ W2, const float* __restrict__ b2,
                       const float* __restrict__ g, const float* __restrict__ bb,
                       float* __restrict__ out) {
    size_t tok = blockIdx.x;
    int tx = threadIdx.x;  // 256
    __shared__ float hrow[64];
    __shared__ float f1[256];
    __shared__ float part[256];
    __shared__ float red[64];
    if (tx < 64) hrow[tx] = d_h2[tok*64 + tx];
    __syncthreads();
    float a = b1[tx];
#pragma unroll
    for (int i = 0; i < 64; i++) a += hrow[i] * W1[i*Fdim + tx];
    // exact GELU
    f1[tx] = 0.5f * a * (1.0f + erff(a * 0.7071067811865476f));
    __syncthreads();
    // W2 stage: 4-way split over j
    int d = tx & 63, gidx = tx >> 6;
    float o = 0.f;
    int jb = gidx * 64;
#pragma unroll 16
    for (int j = 0; j < 64; j++) o += f1[jb + j] * W2[(jb + j)*64 + d];
    part[tx] = o;
    __syncthreads();
    float y = 0.f;
    if (tx < 64) {
        y = part[tx] + part[tx+64] + part[tx+128] + part[tx+192]
          + b2[tx] + hrow[tx];
    }
    float mean = reduce64(y, red, tx) * (1.0f/64.f);
    float c = y - mean;
    float var = reduce64((tx < 64) ? c*c : 0.f, red, tx) * (1.0f/64.f);
    if (tx < 64) out[tok*64 + tx] = c * rsqrtf(var + EPS) * g[tx] + bb[tx];
}

// ---------------- launch: no __device__ symbol ever passed from host ----------------
extern "C" void kernel_launch(void* const* d_in, const int* in_sizes, int n_in,
                              void* d_out, int out_size) {
    const float* x   = (const float*)d_in[0];
    const float* adj = (const float*)d_in[1];
    const float* Wq  = (const float*)d_in[2];
    const float* bq  = (const float*)d_in[3];
    const float* Wk  = (const float*)d_in[4];
    const float* bk  = (const float*)d_in[5];
    const float* Wv  = (const float*)d_in[6];
    const float* bv  = (const float*)d_in[7];
    const float* Wo  = (const float*)d_in[8];
    const float* bo  = (const float*)d_in[9];
    const float* gcW = (const float*)d_in[10];
    const float* gcb = (const float*)d_in[11];
    const float* W1  = (const float*)d_in[12];
    const float* b1  = (const float*)d_in[13];
    const float* W2  = (const float*)d_in[14];
    const float* b2  = (const float*)d_in[15];
    const float* g_t = (const float*)d_in[16];
    const float* b_t = (const float*)d_in[17];
    const float* g_g = (const float*)d_in[18];
    const float* b_g = (const float*)d_in[19];
    const float* g_f = (const float*)d_in[20];
    const float* b_f = (const float*)d_in[21];
    float* out = (float*)d_out;

    // adjacency normalization
    deg_kernel<<<Ndim, 256>>>(adj);
    ahat_kernel<<<Ndim, Ndim>>>(adj);

    // fused QKV projections
    qkv_gemm<<<MTOK/64, 256>>>(x, Wq, bq, Wk, bk, Wv, bv);

    // temporal attention
    attn_kernel<<<Bdim*Ndim, 256>>>();

    // output projection + residual + LN
    oproj_ln<<<MTOK, 64>>>(x, Wo, bo, g_t, b_t);

    // K-hop graph conv
    {
        dim3 grid(8, Bdim*Tdim);
        graph_gemm<<<grid, 256>>>(0);
        graph_gemm<<<grid, 256>>>(1);
    }
    gcomb_ln<<<MTOK, 64>>>(gcW, gcb, g_g, b_g);

    // FFN + residual + LN
    ffn_ln<<<MTOK, 256>>>(W1, b1, W2, b2, g_f, b_f, out);
}

// round 4
// speedup vs baseline: 1.7526x; 1.7526x over previous
#include <cuda_runtime.h>
#include <cuda_bf16.h>
#include <math.h>

#define Bdim 16
#define Tdim 24
#define Ndim 512
#define Ddim 64
#define Hdim 4
#define HD   16
#define Fdim 256
#define MTOK (Bdim*Tdim*Ndim)   // 196608
#define EPS  1e-5f

// ---------------- scratch (referenced ONLY from device code) ----------------
__device__ float d_q[MTOK*Ddim];
__device__ float d_k[MTOK*Ddim];
__device__ float d_v[MTOK*Ddim];
__device__ float d_att[MTOK*Ddim];
__device__ float d_h[MTOK*Ddim];
__device__ float d_p1[MTOK*Ddim];
__device__ float d_p2[MTOK*Ddim];
__device__ float d_h2[MTOK*Ddim];
__device__ float d_Ahat[Ndim*Ndim];
__device__ float d_dinv[Ndim];

// ---------------- degree / Ahat ----------------
__global__ void deg_kernel(const float* __restrict__ adj) {
    int m = blockIdx.x, tx = threadIdx.x;
    float s = 0.f;
    for (int n = tx; n < Ndim; n += 256) s += adj[m*Ndim + n];
    __shared__ float red[256];
    red[tx] = s; __syncthreads();
#pragma unroll
    for (int st = 128; st > 0; st >>= 1) {
        if (tx < st) red[tx] += red[tx + st];
        __syncthreads();
    }
    if (tx == 0) d_dinv[m] = rsqrtf(fmaxf(red[0] + 1.0f, 1e-12f));
}

__global__ void ahat_kernel(const float* __restrict__ adj) {
    int m = blockIdx.x, n = threadIdx.x;
    float a = adj[m*Ndim + n] + (m == n ? 1.0f : 0.0f);
    d_Ahat[m*Ndim + n] = d_dinv[m] * a * d_dinv[n];
}

// ---------------- fused QKV ----------------
__global__ void qkv_gemm(const float* __restrict__ x,
                         const float* __restrict__ Wq, const float* __restrict__ bq,
                         const float* __restrict__ Wk, const float* __restrict__ bk,
                         const float* __restrict__ Wv, const float* __restrict__ bv) {
    __shared__ float As[64][65];
    __shared__ float Ws[64][65];
    int tx = threadIdx.x;
    size_t mbase = (size_t)blockIdx.x * 64;
#pragma unroll 4
    for (int i = tx; i < 4096; i += 256) {
        int r = i >> 6, c = i & 63;
        As[r][c] = x[(mbase + r)*64 + c];
    }
    int r0 = (tx >> 4) * 4, c0 = (tx & 15) * 4;
    const float* Wm[3] = {Wq, Wk, Wv};
    const float* bm[3] = {bq, bk, bv};
    float* Om[3] = {d_q, d_k, d_v};
#pragma unroll
    for (int m = 0; m < 3; m++) {
        __syncthreads();
        const float* W = Wm[m];
#pragma unroll 4
        for (int i = tx; i < 4096; i += 256) {
            int r = i >> 6, c = i & 63;
            Ws[r][c] = W[r*64 + c];
        }
        __syncthreads();
        float acc[4][4] = {};
#pragma unroll
        for (int kk = 0; kk < 64; kk++) {
            float a0 = As[r0+0][kk], a1 = As[r0+1][kk], a2 = As[r0+2][kk], a3 = As[r0+3][kk];
            float w0 = Ws[kk][c0+0], w1 = Ws[kk][c0+1], w2 = Ws[kk][c0+2], w3 = Ws[kk][c0+3];
            acc[0][0] += a0*w0; acc[0][1] += a0*w1; acc[0][2] += a0*w2; acc[0][3] += a0*w3;
            acc[1][0] += a1*w0; acc[1][1] += a1*w1; acc[1][2] += a1*w2; acc[1][3] += a1*w3;
            acc[2][0] += a2*w0; acc[2][1] += a2*w1; acc[2][2] += a2*w2; acc[2][3] += a2*w3;
            acc[3][0] += a3*w0; acc[3][1] += a3*w1; acc[3][2] += a3*w2; acc[3][3] += a3*w3;
        }
        float* O = Om[m];
        const float* bias = bm[m];
#pragma unroll
        for (int i = 0; i < 4; i++)
#pragma unroll
            for (int j = 0; j < 4; j++)
                O[(mbase + r0 + i)*64 + c0 + j] = acc[i][j] + bias[c0 + j];
    }
}

// ---------------- temporal attention v2: transposed K (stride 25), float4 V ----------------
__global__ void attn_kernel() {
    int bn = blockIdx.x;
    int b = bn / Ndim, n = bn % Ndim;
    __shared__ float qs[Tdim][Ddim];               // 1536
    __shared__ float kst[Ddim][25];                // transposed K, odd stride
    __shared__ __align__(16) float vs[Tdim][Ddim]; // 1536
    __shared__ float sc[Hdim][Tdim][Tdim];         // 2304
    int tx = threadIdx.x;  // 256
    for (int i = tx; i < Tdim*Ddim; i += 256) {
        int t = i >> 6, d = i & 63;
        size_t off = (((size_t)b*Tdim + t)*Ndim + n)*Ddim + d;
        qs[t][d] = d_q[off];
        kst[d][t] = d_k[off];
        vs[t][d] = d_v[off];
    }
    __syncthreads();
    // scores: lanes vary tk -> kst row reads contiguous, conflict-free
    for (int i = tx; i < Hdim*Tdim*Tdim; i += 256) {
        int h = i / (Tdim*Tdim), r = i % (Tdim*Tdim);
        int tq = r / Tdim, tk = r % Tdim;
        float s = 0.f;
#pragma unroll
        for (int d = 0; d < HD; d++) s += qs[tq][h*HD + d] * kst[h*HD + d][tk];
        sc[h][tq][tk] = s * 0.25f;
    }
    __syncthreads();
    if (tx < Hdim*Tdim) {
        int h = tx / Tdim, tq = tx % Tdim;
        float m = -1e30f;
#pragma unroll
        for (int tk = 0; tk < Tdim; tk++) m = fmaxf(m, sc[h][tq][tk]);
        float sum = 0.f;
#pragma unroll
        for (int tk = 0; tk < Tdim; tk++) {
            float e = __expf(sc[h][tq][tk] - m);
            sc[h][tq][tk] = e; sum += e;
        }
        float inv = 1.0f / sum;
#pragma unroll
        for (int tk = 0; tk < Tdim; tk++) sc[h][tq][tk] *= inv;
    }
    __syncthreads();
    // V-apply: float4 over d
    const float4* vs4 = (const float4*)&vs[0][0];
    float4* att4 = (float4*)d_att;
    for (int i = tx; i < Tdim*16; i += 256) {
        int tq = i >> 4, d4 = i & 15;
        int h = d4 >> 2;
        float4 o = make_float4(0.f, 0.f, 0.f, 0.f);
#pragma unroll
        for (int tk = 0; tk < Tdim; tk++) {
            float s = sc[h][tq][tk];
            float4 vv = vs4[tk*16 + d4];
            o.x += s*vv.x; o.y += s*vv.y; o.z += s*vv.z; o.w += s*vv.w;
        }
        size_t off4 = (((size_t)b*Tdim + tq)*Ndim + n)*16 + d4;
        att4[off4] = o;
    }
}

// ---------------- tiled O-proj + residual + LN -> d_h ----------------
__global__ void oproj_ln(const float* __restrict__ x,
                         const float* __restrict__ Wo, const float* __restrict__ bo,
                         const float* __restrict__ g, const float* __restrict__ bb) {
    __shared__ float sm[4160*2 + 256 + 256 + 64 + 64];
    float* As = sm;              // [64][65], aliased by ys later
    float* Ws = sm + 4160;       // [64][65]
    float* ys = sm;              // alias As
    float* part_s = sm + 8320;
    float* part_q = sm + 8576;
    float* mu = sm + 8832;
    float* rs = sm + 8896;
    int tx = threadIdx.x;
    size_t mbase = (size_t)blockIdx.x * 64;
#pragma unroll 4
    for (int i = tx; i < 4096; i += 256) {
        int r = i >> 6, c = i & 63;
        As[r*65 + c] = d_att[(mbase + r)*64 + c];
        Ws[r*65 + c] = Wo[r*64 + c];
    }
    __syncthreads();
    int r0 = (tx >> 4) * 4, c0 = (tx & 15) * 4;
    float acc[4][4];
#pragma unroll
    for (int i = 0; i < 4; i++)
#pragma unroll
        for (int j = 0; j < 4; j++)
            acc[i][j] = x[(mbase + r0 + i)*64 + c0 + j] + bo[c0 + j];
#pragma unroll
    for (int kk = 0; kk < 64; kk++) {
        float a0 = As[(r0+0)*65+kk], a1 = As[(r0+1)*65+kk], a2 = As[(r0+2)*65+kk], a3 = As[(r0+3)*65+kk];
        float w0 = Ws[kk*65+c0+0], w1 = Ws[kk*65+c0+1], w2 = Ws[kk*65+c0+2], w3 = Ws[kk*65+c0+3];
        acc[0][0] += a0*w0; acc[0][1] += a0*w1; acc[0][2] += a0*w2; acc[0][3] += a0*w3;
        acc[1][0] += a1*w0; acc[1][1] += a1*w1; acc[1][2] += a1*w2; acc[1][3] += a1*w3;
        acc[2][0] += a2*w0; acc[2][1] += a2*w1; acc[2][2] += a2*w2; acc[2][3] += a2*w3;
        acc[3][0] += a3*w0; acc[3][1] += a3*w1; acc[3][2] += a3*w2; acc[3][3] += a3*w3;
    }
    __syncthreads();   // all GEMM reads of As done
#pragma unroll
    for (int i = 0; i < 4; i++)
#pragma unroll
        for (int j = 0; j < 4; j++)
            ys[(r0+i)*65 + c0 + j] = acc[i][j];
    __syncthreads();
    {
        int row = tx >> 2, seg = tx & 3;
        float s = 0.f, q = 0.f;
#pragma unroll
        for (int cc = 0; cc < 16; cc++) {
            float v = ys[row*65 + seg*16 + cc];
            s += v; q += v*v;
        }
        part_s[tx] = s; part_q[tx] = q;
    }
    __syncthreads();
    if (tx < 64) {
        float S = part_s[tx*4] + part_s[tx*4+1] + part_s[tx*4+2] + part_s[tx*4+3];
        float Q = part_q[tx*4] + part_q[tx*4+1] + part_q[tx*4+2] + part_q[tx*4+3];
        float m = S * (1.0f/64.f);
        float var = Q * (1.0f/64.f) - m*m;
        mu[tx] = m; rs[tx] = rsqrtf(var + EPS);
    }
    __syncthreads();
#pragma unroll
    for (int i = 0; i < 4; i++) {
        int row = r0 + i;
#pragma unroll
        for (int j = 0; j < 4; j++) {
            int col = c0 + j;
            d_h[(mbase + row)*64 + col] = (ys[row*65 + col] - mu[row]) * rs[row] * g[col] + bb[col];
        }
    }
}

// ---------------- graph GEMM: stage 0: p1 = Ahat@h ; stage 1: p2 = Ahat@p1 ----------------
__global__ void graph_gemm(int stage) {
    const float* __restrict__ Hin = stage ? (const float*)d_p1 : (const float*)d_h;
    float* __restrict__ Hout      = stage ? d_p2 : d_p1;
    __shared__ float As[64][65];
    __shared__ float Bs[64][65];
    int tx = threadIdx.x;
    int mbase = blockIdx.x * 64;
    size_t hbase = (size_t)blockIdx.y * Ndim * Ddim;
    int r0 = (tx >> 4) * 4, c0 = (tx & 15) * 4;
    float acc[4][4] = {};
    for (int kt = 0; kt < 8; kt++) {
#pragma unroll 4
        for (int i = tx; i < 4096; i += 256) {
            int r = i >> 6, c = i & 63;
            As[r][c] = d_Ahat[(size_t)(mbase + r)*Ndim + kt*64 + c];
            Bs[r][c] = Hin[hbase + (size_t)(kt*64 + r)*64 + c];
        }
        __syncthreads();
#pragma unroll
        for (int kk = 0; kk < 64; kk++) {
            float a0 = As[r0+0][kk], a1 = As[r0+1][kk], a2 = As[r0+2][kk], a3 = As[r0+3][kk];
            float w0 = Bs[kk][c0+0], w1 = Bs[kk][c0+1], w2 = Bs[kk][c0+2], w3 = Bs[kk][c0+3];
            acc[0][0] += a0*w0; acc[0][1] += a0*w1; acc[0][2] += a0*w2; acc[0][3] += a0*w3;
            acc[1][0] += a1*w0; acc[1][1] += a1*w1; acc[1][2] += a1*w2; acc[1][3] += a1*w3;
            acc[2][0] += a2*w0; acc[2][1] += a2*w1; acc[2][2] += a2*w2; acc[2][3] += a2*w3;
            acc[3][0] += a3*w0; acc[3][1] += a3*w1; acc[3][2] += a3*w2; acc[3][3] += a3*w3;
        }
        __syncthreads();
    }
#pragma unroll
    for (int i = 0; i < 4; i++)
#pragma unroll
        for (int j = 0; j < 4; j++)
            Hout[hbase + (size_t)(mbase + r0 + i)*64 + c0 + j] = acc[i][j];
}

// ---------------- tiled gc combine (K=192) + residual + LN -> d_h2 ----------------
__global__ void gcomb_ln(const float* __restrict__ gcW, const float* __restrict__ gcb,
                         const float* __restrict__ g, const float* __restrict__ bb) {
    __shared__ float sm[4160*2 + 256 + 256 + 64 + 64];
    float* In = sm;              // [64][65], aliased by ys
    float* Ws = sm + 4160;
    float* ys = sm;
    float* part_s = sm + 8320;
    float* part_q = sm + 8576;
    float* mu = sm + 8832;
    float* rs = sm + 8896;
    int tx = threadIdx.x;
    size_t mbase = (size_t)blockIdx.x * 64;
    int r0 = (tx >> 4) * 4, c0 = (tx & 15) * 4;
    float acc[4][4] = {};
#pragma unroll
    for (int s = 0; s < 3; s++) {
        const float* Hin = (s == 0) ? (const float*)d_h : (s == 1) ? (const float*)d_p1 : (const float*)d_p2;
        __syncthreads();   // previous readers done
#pragma unroll 4
        for (int i = tx; i < 4096; i += 256) {
            int r = i >> 6, c = i & 63;
            In[r*65 + c] = Hin[(mbase + r)*64 + c];
            Ws[r*65 + c] = gcW[s*4096 + r*64 + c];
        }
        __syncthreads();
        if (s == 0) {   // residual: +h
#pragma unroll
            for (int i = 0; i < 4; i++)
#pragma unroll
                for (int j = 0; j < 4; j++)
                    acc[i][j] += In[(r0+i)*65 + c0 + j];
        }
#pragma unroll
        for (int kk = 0; kk < 64; kk++) {
            float a0 = In[(r0+0)*65+kk], a1 = In[(r0+1)*65+kk], a2 = In[(r0+2)*65+kk], a3 = In[(r0+3)*65+kk];
            float w0 = Ws[kk*65+c0+0], w1 = Ws[kk*65+c0+1], w2 = Ws[kk*65+c0+2], w3 = Ws[kk*65+c0+3];
            acc[0][0] += a0*w0; acc[0][1] += a0*w1; acc[0][2] += a0*w2; acc[0][3] += a0*w3;
            acc[1][0] += a1*w0; acc[1][1] += a1*w1; acc[1][2] += a1*w2; acc[1][3] += a1*w3;
            acc[2][0] += a2*w0; acc[2][1] += a2*w1; acc[2][2] += a2*w2; acc[2][3] += a2*w3;
            acc[3][0] += a3*w0; acc[3][1] += a3*w1; acc[3][2] += a3*w2; acc[3][3] += a3*w3;
        }
    }
    __syncthreads();
#pragma unroll
    for (int i = 0; i < 4; i++)
#pragma unroll
        for (int j = 0; j < 4; j++)
            ys[(r0+i)*65 + c0 + j] = acc[i][j] + gcb[c0+j] + gcb[64 + c0+j] + gcb[128 + c0+j];
    __syncthreads();
    {
        int row = tx >> 2, seg = tx & 3;
        float s = 0.f, q = 0.f;
#pragma unroll
        for (int cc = 0; cc < 16; cc++) {
            float v = ys[row*65 + seg*16 + cc];
            s += v; q += v*v;
        }
        part_s[tx] = s; part_q[tx] = q;
    }
    __syncthreads();
    if (tx < 64) {
        float S = part_s[tx*4] + part_s[tx*4+1] + part_s[tx*4+2] + part_s[tx*4+3];
        float Q = part_q[tx*4] + part_q[tx*4+1] + part_q[tx*4+2] + part_q[tx*4+3];
        float m = S * (1.0f/64.f);
        float var = Q * (1.0f/64.f) - m*m;
        mu[tx] = m; rs[tx] = rsqrtf(var + EPS);
    }
    __syncthreads();
#pragma unroll
    for (int i = 0; i < 4; i++) {
        int row = r0 + i;
#pragma unroll
        for (int j = 0; j < 4; j++) {
            int col = c0 + j;
            d_h2[(mbase + row)*64 + col] = (ys[row*65 + col] - mu[row]) * rs[row] * g[col] + bb[col];
        }
    }
}

// ---------------- tiled FFN + residual + LN -> out ----------------
__global__ void ffn_ln(const float* __restrict__ W1, const float* __restrict__ b1,
                       const float* __restrict__ W2, const float* __restrict__ b2,
                       const float* __restrict__ g, const float* __restrict__ bb,
                       float* __restrict__ out) {
    __shared__ float sm[12288];  // 48KB exactly
    float* A  = sm;          // [64][64] input tile (h2), later aliased by ys
    float* Wt = sm + 4096;   // [64][64] weight chunk, later aliased by reduction arrays
    float* Gc = sm + 8192;   // [64][64] gelu chunk
    float* ys = A;
    float* part_s = Wt;          // 256
    float* part_q = Wt + 256;    // 256
    float* mu = Wt + 512;        // 64
    float* rs = Wt + 576;        // 64
    int tx = threadIdx.x;
    size_t mbase = (size_t)blockIdx.x * 64;
    int r0 = (tx >> 4) * 4, c0 = (tx & 15) * 4;
#pragma unroll 4
    for (int i = tx; i < 4096; i += 256)
        A[i] = d_h2[mbase*64 + i];
    float acc[4][4] = {};
#pragma unroll
    for (int c = 0; c < 4; c++) {
        __syncthreads();   // A ready (c=0) / Wt & Gc readers done (c>0)
#pragma unroll 4
        for (int i = tx; i < 4096; i += 256) {
            int kk = i >> 6, col = i & 63;
            Wt[i] = W1[kk*Fdim + c*64 + col];
        }
        __syncthreads();
        // phase1: P = A @ W1c, gelu -> Gc
        {
            float p[4][4] = {};
#pragma unroll
            for (int kk = 0; kk < 64; kk++) {
                float a0 = A[(r0+0)*64+kk], a1 = A[(r0+1)*64+kk], a2 = A[(r0+2)*64+kk], a3 = A[(r0+3)*64+kk];
                float w0 = Wt[kk*64+c0+0], w1 = Wt[kk*64+c0+1], w2 = Wt[kk*64+c0+2], w3 = Wt[kk*64+c0+3];
                p[0][0] += a0*w0; p[0][1] += a0*w1; p[0][2] += a0*w2; p[0][3] += a0*w3;
                p[1][0] += a1*w0; p[1][1] += a1*w1; p[1][2] += a1*w2; p[1][3] += a1*w3;
                p[2][0] += a2*w0; p[2][1] += a2*w1; p[2][2] += a2*w2; p[2][3] += a2*w3;
                p[3][0] += a3*w0; p[3][1] += a3*w1; p[3][2] += a3*w2; p[3][3] += a3*w3;
            }
#pragma unroll
            for (int i = 0; i < 4; i++)
#pragma unroll
                for (int j = 0; j < 4; j++) {
                    float a = p[i][j] + b1[c*64 + c0 + j];
                    Gc[(r0+i)*64 + c0 + j] = 0.5f * a * (1.0f + erff(a * 0.7071067811865476f));
                }
        }
        __syncthreads();
#pragma unroll 4
        for (int i = tx; i < 4096; i += 256)
            Wt[i] = W2[c*4096 + i];
        __syncthreads();
        // phase2: acc += Gc @ W2c
#pragma unroll
        for (int kk = 0; kk < 64; kk++) {
            float a0 = Gc[(r0+0)*64+kk], a1 = Gc[(r0+1)*64+kk], a2 = Gc[(r0+2)*64+kk], a3 = Gc[(r0+3)*64+kk];
            float w0 = Wt[kk*64+c0+0], w1 = Wt[kk*64+c0+1], w2 = Wt[kk*64+c0+2], w3 = Wt[kk*64+c0+3];
            acc[0][0] += a0*w0; acc[0][1] += a0*w1; acc[0][2] += a0*w2; acc[0][3] += a0*w3;
            acc[1][0] += a1*w0; acc[1][1] += a1*w1; acc[1][2] += a1*w2; acc[1][3] += a1*w3;
            acc[2][0] += a2*w0; acc[2][1] += a2*w1; acc[2][2] += a2*w2; acc[2][3] += a2*w3;
            acc[3][0] += a3*w0; acc[3][1] += a3*w1; acc[3][2] += a3*w2; acc[3][3] += a3*w3;
        }
    }
    __syncthreads();
    // y = acc + b2 + residual(h2 = A); each thread touches only its own elements of A
#pragma unroll
    for (int i = 0; i < 4; i++)
#pragma unroll
        for (int j = 0; j < 4; j++) {
            int idx = (r0+i)*64 + c0 + j;
            ys[idx] = acc[i][j] + b2[c0+j] + A[idx];
        }
    __syncthreads();
    {
        int row = tx >> 2, seg = tx & 3;
        float s = 0.f, q = 0.f;
#pragma unroll
        for (int cc = 0; cc < 16; cc++) {
            float v = ys[row*64 + seg*16 + cc];
            s += v; q += v*v;
        }
        part_s[tx] = s; part_q[tx] = q;
    }
    __syncthreads();
    if (tx < 64) {
        float S = part_s[tx*4] + part_s[tx*4+1] + part_s[tx*4+2] + part_s[tx*4+3];
        float Q = part_q[tx*4] + part_q[tx*4+1] + part_q[tx*4+2] + part_q[tx*4+3];
        float m = S * (1.0f/64.f);
        float var = Q * (1.0f/64.f) - m*m;
        mu[tx] = m; rs[tx] = rsqrtf(var + EPS);
    }
    __syncthreads();
#pragma unroll
    for (int i = 0; i < 4; i++) {
        int row = r0 + i;
#pragma unroll
        for (int j = 0; j < 4; j++) {
            int col = c0 + j;
            out[(mbase + row)*64 + col] = (ys[row*64 + col] - mu[row]) * rs[row] * g[col] + bb[col];
        }
    }
}

// ---------------- launch ----------------
extern "C" void kernel_launch(void* const* d_in, const int* in_sizes, int n_in,
                              void* d_out, int out_size) {
    const float* x   = (const float*)d_in[0];
    const float* adj = (const float*)d_in[1];
    const float* Wq  = (const float*)d_in[2];
    const float* bq  = (const float*)d_in[3];
    const float* Wk  = (const float*)d_in[4];
    const float* bk  = (const float*)d_in[5];
    const float* Wv  = (const float*)d_in[6];
    const float* bv  = (const float*)d_in[7];
    const float* Wo  = (const float*)d_in[8];
    const float* bo  = (const float*)d_in[9];
    const float* gcW = (const float*)d_in[10];
    const float* gcb = (const float*)d_in[11];
    const float* W1  = (const float*)d_in[12];
    const float* b1  = (const float*)d_in[13];
    const float* W2  = (const float*)d_in[14];
    const float* b2  = (const float*)d_in[15];
    const float* g_t = (const float*)d_in[16];
    const float* b_t = (const float*)d_in[17];
    const float* g_g = (const float*)d_in[18];
    const float* b_g = (const float*)d_in[19];
    const float* g_f = (const float*)d_in[20];
    const float* b_f = (const float*)d_in[21];
    float* out = (float*)d_out;

    deg_kernel<<<Ndim, 256>>>(adj);
    ahat_kernel<<<Ndim, Ndim>>>(adj);

    qkv_gemm<<<MTOK/64, 256>>>(x, Wq, bq, Wk, bk, Wv, bv);

    attn_kernel<<<Bdim*Ndim, 256>>>();

    oproj_ln<<<MTOK/64, 256>>>(x, Wo, bo, g_t, b_t);

    {
        dim3 grid(8, Bdim*Tdim);
        graph_gemm<<<grid, 256>>>(0);
        graph_gemm<<<grid, 256>>>(1);
    }
    gcomb_ln<<<MTOK/64, 256>>>(gcW, gcb, g_g, b_g);

    ffn_ln<<<MTOK/64, 256>>>(W1, b1, W2, b2, g_f, b_f, out);
}

// round 5
// speedup vs baseline: 2.3064x; 1.3160x over previous
#include <cuda_runtime.h>
#include <cuda_bf16.h>
#include <math.h>

#define Bdim 16
#define Tdim 24
#define Ndim 512
#define Ddim 64
#define Hdim 4
#define HD   16
#define Fdim 256
#define MTOK (Bdim*Tdim*Ndim)   // 196608
#define EPS  1e-5f

// XOR-quad swizzle for stride-64 fp32/tf32 smem tiles: conflict-free a-frag loads
#define IDX(r,c) (((r)<<6) | (((c)&3) | (((((c)>>2) ^ ((r)&7))&15) << 2)))

// ---------------- scratch (device-only references) ----------------
__device__ float d_q[MTOK*Ddim];
__device__ float d_k[MTOK*Ddim];
__device__ float d_v[MTOK*Ddim];
__device__ float d_att[MTOK*Ddim];
__device__ float d_h[MTOK*Ddim];
__device__ float d_p1[MTOK*Ddim];
__device__ float d_p2[MTOK*Ddim];
__device__ float d_h2[MTOK*Ddim];
__device__ float d_Ahat[Ndim*Ndim];
__device__ float d_dinv[Ndim];

__device__ __forceinline__ unsigned f2tf32(float x) {
    unsigned r;
    asm("cvt.rna.tf32.f32 %0, %1;" : "=r"(r) : "f"(x));
    return r;
}

__device__ __forceinline__ void mma_tf32(float c[4], unsigned a0, unsigned a1,
                                         unsigned a2, unsigned a3,
                                         unsigned b0, unsigned b1) {
    asm volatile(
        "mma.sync.aligned.m16n8k8.row.col.f32.tf32.tf32.f32 "
        "{%0,%1,%2,%3}, {%4,%5,%6,%7}, {%8,%9}, {%0,%1,%2,%3};"
        : "+f"(c[0]), "+f"(c[1]), "+f"(c[2]), "+f"(c[3])
        : "r"(a0), "r"(a1), "r"(a2), "r"(a3), "r"(b0), "r"(b1));
}

// ---------------- degree / Ahat ----------------
__global__ void deg_kernel(const float* __restrict__ adj) {
    int m = blockIdx.x, tx = threadIdx.x;
    float s = 0.f;
    for (int n = tx; n < Ndim; n += 256) s += adj[m*Ndim + n];
    __shared__ float red[256];
    red[tx] = s; __syncthreads();
#pragma unroll
    for (int st = 128; st > 0; st >>= 1) {
        if (tx < st) red[tx] += red[tx + st];
        __syncthreads();
    }
    if (tx == 0) d_dinv[m] = rsqrtf(fmaxf(red[0] + 1.0f, 1e-12f));
}

__global__ void ahat_kernel(const float* __restrict__ adj) {
    int m = blockIdx.x, n = threadIdx.x;
    float a = adj[m*Ndim + n] + (m == n ? 1.0f : 0.0f);
    d_Ahat[m*Ndim + n] = d_dinv[m] * a * d_dinv[n];
}

// ---------------- fused QKV (FFMA; ~160us) ----------------
__global__ void qkv_gemm(const float* __restrict__ x,
                         const float* __restrict__ Wq, const float* __restrict__ bq,
                         const float* __restrict__ Wk, const float* __restrict__ bk,
                         const float* __restrict__ Wv, const float* __restrict__ bv) {
    __shared__ float As[64][65];
    __shared__ float Ws[64][65];
    int tx = threadIdx.x;
    size_t mbase = (size_t)blockIdx.x * 64;
#pragma unroll 4
    for (int i = tx; i < 4096; i += 256) {
        int r = i >> 6, c = i & 63;
        As[r][c] = x[(mbase + r)*64 + c];
    }
    int r0 = (tx >> 4) * 4, c0 = (tx & 15) * 4;
    const float* Wm[3] = {Wq, Wk, Wv};
    const float* bm[3] = {bq, bk, bv};
    float* Om[3] = {d_q, d_k, d_v};
#pragma unroll
    for (int m = 0; m < 3; m++) {
        __syncthreads();
        const float* W = Wm[m];
#pragma unroll 4
        for (int i = tx; i < 4096; i += 256) {
            int r = i >> 6, c = i & 63;
            Ws[r][c] = W[r*64 + c];
        }
        __syncthreads();
        float acc[4][4] = {};
#pragma unroll
        for (int kk = 0; kk < 64; kk++) {
            float a0 = As[r0+0][kk], a1 = As[r0+1][kk], a2 = As[r0+2][kk], a3 = As[r0+3][kk];
            float w0 = Ws[kk][c0+0], w1 = Ws[kk][c0+1], w2 = Ws[kk][c0+2], w3 = Ws[kk][c0+3];
            acc[0][0] += a0*w0; acc[0][1] += a0*w1; acc[0][2] += a0*w2; acc[0][3] += a0*w3;
            acc[1][0] += a1*w0; acc[1][1] += a1*w1; acc[1][2] += a1*w2; acc[1][3] += a1*w3;
            acc[2][0] += a2*w0; acc[2][1] += a2*w1; acc[2][2] += a2*w2; acc[2][3] += a2*w3;
            acc[3][0] += a3*w0; acc[3][1] += a3*w1; acc[3][2] += a3*w2; acc[3][3] += a3*w3;
        }
        float* O = Om[m];
        const float* bias = bm[m];
#pragma unroll
        for (int i = 0; i < 4; i++)
#pragma unroll
            for (int j = 0; j < 4; j++)
                O[(mbase + r0 + i)*64 + c0 + j] = acc[i][j] + bias[c0 + j];
    }
}

// ---------------- temporal attention (unchanged) ----------------
__global__ void attn_kernel() {
    int bn = blockIdx.x;
    int b = bn / Ndim, n = bn % Ndim;
    __shared__ float qs[Tdim][Ddim];
    __shared__ float kst[Ddim][25];
    __shared__ __align__(16) float vs[Tdim][Ddim];
    __shared__ float sc[Hdim][Tdim][Tdim];
    int tx = threadIdx.x;
    for (int i = tx; i < Tdim*Ddim; i += 256) {
        int t = i >> 6, d = i & 63;
        size_t off = (((size_t)b*Tdim + t)*Ndim + n)*Ddim + d;
        qs[t][d] = d_q[off];
        kst[d][t] = d_k[off];
        vs[t][d] = d_v[off];
    }
    __syncthreads();
    for (int i = tx; i < Hdim*Tdim*Tdim; i += 256) {
        int h = i / (Tdim*Tdim), r = i % (Tdim*Tdim);
        int tq = r / Tdim, tk = r % Tdim;
        float s = 0.f;
#pragma unroll
        for (int d = 0; d < HD; d++) s += qs[tq][h*HD + d] * kst[h*HD + d][tk];
        sc[h][tq][tk] = s * 0.25f;
    }
    __syncthreads();
    if (tx < Hdim*Tdim) {
        int h = tx / Tdim, tq = tx % Tdim;
        float m = -1e30f;
#pragma unroll
        for (int tk = 0; tk < Tdim; tk++) m = fmaxf(m, sc[h][tq][tk]);
        float sum = 0.f;
#pragma unroll
        for (int tk = 0; tk < Tdim; tk++) {
            float e = __expf(sc[h][tq][tk] - m);
            sc[h][tq][tk] = e; sum += e;
        }
        float inv = 1.0f / sum;
#pragma unroll
        for (int tk = 0; tk < Tdim; tk++) sc[h][tq][tk] *= inv;
    }
    __syncthreads();
    const float4* vs4 = (const float4*)&vs[0][0];
    float4* att4 = (float4*)d_att;
    for (int i = tx; i < Tdim*16; i += 256) {
        int tq = i >> 4, d4 = i & 15;
        int h = d4 >> 2;
        float4 o = make_float4(0.f, 0.f, 0.f, 0.f);
#pragma unroll
        for (int tk = 0; tk < Tdim; tk++) {
            float s = sc[h][tq][tk];
            float4 vv = vs4[tk*16 + d4];
            o.x += s*vv.x; o.y += s*vv.y; o.z += s*vv.z; o.w += s*vv.w;
        }
        size_t off4 = (((size_t)b*Tdim + tq)*Ndim + n)*16 + d4;
        att4[off4] = o;
    }
}

// ---------------- tiled O-proj + residual + LN (unchanged FFMA) ----------------
__global__ void oproj_ln(const float* __restrict__ x,
                         const float* __restrict__ Wo, const float* __restrict__ bo,
                         const float* __restrict__ g, const float* __restrict__ bb) {
    __shared__ float sm[4160*2 + 256 + 256 + 64 + 64];
    float* As = sm;
    float* Ws = sm + 4160;
    float* ys = sm;
    float* part_s = sm + 8320;
    float* part_q = sm + 8576;
    float* mu = sm + 8832;
    float* rs = sm + 8896;
    int tx = threadIdx.x;
    size_t mbase = (size_t)blockIdx.x * 64;
#pragma unroll 4
    for (int i = tx; i < 4096; i += 256) {
        int r = i >> 6, c = i & 63;
        As[r*65 + c] = d_att[(mbase + r)*64 + c];
        Ws[r*65 + c] = Wo[r*64 + c];
    }
    __syncthreads();
    int r0 = (tx >> 4) * 4, c0 = (tx & 15) * 4;
    float acc[4][4];
#pragma unroll
    for (int i = 0; i < 4; i++)
#pragma unroll
        for (int j = 0; j < 4; j++)
            acc[i][j] = x[(mbase + r0 + i)*64 + c0 + j] + bo[c0 + j];
#pragma unroll
    for (int kk = 0; kk < 64; kk++) {
        float a0 = As[(r0+0)*65+kk], a1 = As[(r0+1)*65+kk], a2 = As[(r0+2)*65+kk], a3 = As[(r0+3)*65+kk];
        float w0 = Ws[kk*65+c0+0], w1 = Ws[kk*65+c0+1], w2 = Ws[kk*65+c0+2], w3 = Ws[kk*65+c0+3];
        acc[0][0] += a0*w0; acc[0][1] += a0*w1; acc[0][2] += a0*w2; acc[0][3] += a0*w3;
        acc[1][0] += a1*w0; acc[1][1] += a1*w1; acc[1][2] += a1*w2; acc[1][3] += a1*w3;
        acc[2][0] += a2*w0; acc[2][1] += a2*w1; acc[2][2] += a2*w2; acc[2][3] += a2*w3;
        acc[3][0] += a3*w0; acc[3][1] += a3*w1; acc[3][2] += a3*w2; acc[3][3] += a3*w3;
    }
    __syncthreads();
#pragma unroll
    for (int i = 0; i < 4; i++)
#pragma unroll
        for (int j = 0; j < 4; j++)
            ys[(r0+i)*65 + c0 + j] = acc[i][j];
    __syncthreads();
    {
        int row = tx >> 2, seg = tx & 3;
        float s = 0.f, q = 0.f;
#pragma unroll
        for (int cc = 0; cc < 16; cc++) {
            float v = ys[row*65 + seg*16 + cc];
            s += v; q += v*v;
        }
        part_s[tx] = s; part_q[tx] = q;
    }
    __syncthreads();
    if (tx < 64) {
        float S = part_s[tx*4] + part_s[tx*4+1] + part_s[tx*4+2] + part_s[tx*4+3];
        float Q = part_q[tx*4] + part_q[tx*4+1] + part_q[tx*4+2] + part_q[tx*4+3];
        float m = S * (1.0f/64.f);
        float var = Q * (1.0f/64.f) - m*m;
        mu[tx] = m; rs[tx] = rsqrtf(var + EPS);
    }
    __syncthreads();
#pragma unroll
    for (int i = 0; i < 4; i++) {
        int row = r0 + i;
#pragma unroll
        for (int j = 0; j < 4; j++) {
            int col = c0 + j;
            d_h[(mbase + row)*64 + col] = (ys[row*65 + col] - mu[row]) * rs[row] * g[col] + bb[col];
        }
    }
}

// ---------------- graph GEMM via tf32 tensor mma ----------------
// out[bt, m, :] = sum_n Ahat[m,n] * in[bt, n, :]
__global__ void graph_gemm_tf32(int stage) {
    const float* __restrict__ Hin = stage ? (const float*)d_p1 : (const float*)d_h;
    float* __restrict__ Hout      = stage ? d_p2 : d_p1;
    __shared__ unsigned As[4096];   // tf32 bits, swizzled  (m x k tile of Ahat)
    __shared__ unsigned Bs[4096];   // tf32 bits, swizzled  (k x n tile of Hin)
    int tx = threadIdx.x;
    int wid = tx >> 5, lane = tx & 31;
    int mrow = (wid >> 1) * 16, ncol = (wid & 1) * 32;
    int mbase = blockIdx.x * 64;
    size_t hbase = (size_t)blockIdx.y * Ndim * Ddim;
    float acc[4][4] = {};
    for (int kt = 0; kt < 8; kt++) {
        __syncthreads();
#pragma unroll 4
        for (int i = tx; i < 4096; i += 256) {
            int r = i >> 6, c = i & 63;
            As[IDX(r,c)] = f2tf32(d_Ahat[(size_t)(mbase + r)*Ndim + kt*64 + c]);
            Bs[IDX(r,c)] = f2tf32(Hin[hbase + (size_t)(kt*64 + r)*64 + c]);
        }
        __syncthreads();
#pragma unroll
        for (int k8 = 0; k8 < 8; k8++) {
            int kk = k8 * 8;
            int ar = mrow + (lane >> 2), ac = kk + (lane & 3);
            unsigned a0 = As[IDX(ar,   ac)];
            unsigned a1 = As[IDX(ar+8, ac)];
            unsigned a2 = As[IDX(ar,   ac+4)];
            unsigned a3 = As[IDX(ar+8, ac+4)];
#pragma unroll
            for (int nb = 0; nb < 4; nb++) {
                int n0 = ncol + nb*8;
                unsigned b0 = Bs[IDX(kk + (lane & 3),     n0 + (lane >> 2))];
                unsigned b1 = Bs[IDX(kk + (lane & 3) + 4, n0 + (lane >> 2))];
                mma_tf32(acc[nb], a0, a1, a2, a3, b0, b1);
            }
        }
    }
    // epilogue: write c-frags (float2 per row pair of cols)
    int row = mbase + mrow + (lane >> 2);
#pragma unroll
    for (int nb = 0; nb < 4; nb++) {
        int col = ncol + nb*8 + 2*(lane & 3);
        float2* p0 = (float2*)&Hout[hbase + (size_t)row*64 + col];
        float2* p1 = (float2*)&Hout[hbase + (size_t)(row+8)*64 + col];
        *p0 = make_float2(acc[nb][0], acc[nb][1]);
        *p1 = make_float2(acc[nb][2], acc[nb][3]);
    }
}

// ---------------- tiled gc combine + residual + LN (unchanged FFMA) ----------------
__global__ void gcomb_ln(const float* __restrict__ gcW, const float* __restrict__ gcb,
                         const float* __restrict__ g, const float* __restrict__ bb) {
    __shared__ float sm[4160*2 + 256 + 256 + 64 + 64];
    float* In = sm;
    float* Ws = sm + 4160;
    float* ys = sm;
    float* part_s = sm + 8320;
    float* part_q = sm + 8576;
    float* mu = sm + 8832;
    float* rs = sm + 8896;
    int tx = threadIdx.x;
    size_t mbase = (size_t)blockIdx.x * 64;
    int r0 = (tx >> 4) * 4, c0 = (tx & 15) * 4;
    float acc[4][4] = {};
#pragma unroll
    for (int s = 0; s < 3; s++) {
        const float* Hin = (s == 0) ? (const float*)d_h : (s == 1) ? (const float*)d_p1 : (const float*)d_p2;
        __syncthreads();
#pragma unroll 4
        for (int i = tx; i < 4096; i += 256) {
            int r = i >> 6, c = i & 63;
            In[r*65 + c] = Hin[(mbase + r)*64 + c];
            Ws[r*65 + c] = gcW[s*4096 + r*64 + c];
        }
        __syncthreads();
        if (s == 0) {
#pragma unroll
            for (int i = 0; i < 4; i++)
#pragma unroll
                for (int j = 0; j < 4; j++)
                    acc[i][j] += In[(r0+i)*65 + c0 + j];
        }
#pragma unroll
        for (int kk = 0; kk < 64; kk++) {
            float a0 = In[(r0+0)*65+kk], a1 = In[(r0+1)*65+kk], a2 = In[(r0+2)*65+kk], a3 = In[(r0+3)*65+kk];
            float w0 = Ws[kk*65+c0+0], w1 = Ws[kk*65+c0+1], w2 = Ws[kk*65+c0+2], w3 = Ws[kk*65+c0+3];
            acc[0][0] += a0*w0; acc[0][1] += a0*w1; acc[0][2] += a0*w2; acc[0][3] += a0*w3;
            acc[1][0] += a1*w0; acc[1][1] += a1*w1; acc[1][2] += a1*w2; acc[1][3] += a1*w3;
            acc[2][0] += a2*w0; acc[2][1] += a2*w1; acc[2][2] += a2*w2; acc[2][3] += a2*w3;
            acc[3][0] += a3*w0; acc[3][1] += a3*w1; acc[3][2] += a3*w2; acc[3][3] += a3*w3;
        }
    }
    __syncthreads();
#pragma unroll
    for (int i = 0; i < 4; i++)
#pragma unroll
        for (int j = 0; j < 4; j++)
            ys[(r0+i)*65 + c0 + j] = acc[i][j] + gcb[c0+j] + gcb[64 + c0+j] + gcb[128 + c0+j];
    __syncthreads();
    {
        int row = tx >> 2, seg = tx & 3;
        float s = 0.f, q = 0.f;
#pragma unroll
        for (int cc = 0; cc < 16; cc++) {
            float v = ys[row*65 + seg*16 + cc];
            s += v; q += v*v;
        }
        part_s[tx] = s; part_q[tx] = q;
    }
    __syncthreads();
    if (tx < 64) {
        float S = part_s[tx*4] + part_s[tx*4+1] + part_s[tx*4+2] + part_s[tx*4+3];
        float Q = part_q[tx*4] + part_q[tx*4+1] + part_q[tx*4+2] + part_q[tx*4+3];
        float m = S * (1.0f/64.f);
        float var = Q * (1.0f/64.f) - m*m;
        mu[tx] = m; rs[tx] = rsqrtf(var + EPS);
    }
    __syncthreads();
#pragma unroll
    for (int i = 0; i < 4; i++) {
        int row = r0 + i;
#pragma unroll
        for (int j = 0; j < 4; j++) {
            int col = c0 + j;
            d_h2[(mbase + row)*64 + col] = (ys[row*65 + col] - mu[row]) * rs[row] * g[col] + bb[col];
        }
    }
}

// ---------------- FFN via tf32 tensor mma + residual + LN ----------------
__global__ void ffn_ln(const float* __restrict__ W1, const float* __restrict__ b1,
                       const float* __restrict__ W2, const float* __restrict__ b2,
                       const float* __restrict__ g, const float* __restrict__ bb,
                       float* __restrict__ out) {
    __shared__ float    Asm[4096];   // fp32 h2 tile (swizzled) — residual source
    __shared__ unsigned Wt[4096];    // tf32 bits (W1 chunk / W2 chunk), later ys
    __shared__ unsigned Gc[4096];    // tf32 bits gelu output, later LN scratch
    int tx = threadIdx.x;
    int wid = tx >> 5, lane = tx & 31;
    int mrow = (wid >> 1) * 16, ncol = (wid & 1) * 32;
    size_t mbase = (size_t)blockIdx.x * 64;
#pragma unroll 4
    for (int i = tx; i < 4096; i += 256) {
        int r = i >> 6, c = i & 63;
        Asm[IDX(r,c)] = d_h2[(mbase + r)*64 + c];
    }
    float acc[4][4] = {};
#pragma unroll
    for (int ch = 0; ch < 4; ch++) {
        __syncthreads();   // Asm ready (ch=0) / previous phase2 reads of Wt done
#pragma unroll 4
        for (int i = tx; i < 4096; i += 256) {
            int r = i >> 6, c = i & 63;
            Wt[IDX(r,c)] = f2tf32(W1[r*Fdim + ch*64 + c]);
        }
        __syncthreads();
        // phase1: P = A @ W1c
        float p[4][4] = {};
#pragma unroll
        for (int k8 = 0; k8 < 8; k8++) {
            int kk = k8 * 8;
            int ar = mrow + (lane >> 2), ac = kk + (lane & 3);
            unsigned a0 = f2tf32(Asm[IDX(ar,   ac)]);
            unsigned a1 = f2tf32(Asm[IDX(ar+8, ac)]);
            unsigned a2 = f2tf32(Asm[IDX(ar,   ac+4)]);
            unsigned a3 = f2tf32(Asm[IDX(ar+8, ac+4)]);
#pragma unroll
            for (int nb = 0; nb < 4; nb++) {
                int n0 = ncol + nb*8;
                unsigned b0 = Wt[IDX(kk + (lane & 3),     n0 + (lane >> 2))];
                unsigned b1 = Wt[IDX(kk + (lane & 3) + 4, n0 + (lane >> 2))];
                mma_tf32(p[nb], a0, a1, a2, a3, b0, b1);
            }
        }
        // gelu epilogue -> Gc (tf32 bits)
        {
            int row = mrow + (lane >> 2);
#pragma unroll
            for (int nb = 0; nb < 4; nb++) {
                int col = ncol + nb*8 + 2*(lane & 3);
                float bv0 = b1[ch*64 + col], bv1 = b1[ch*64 + col + 1];
                float v0 = p[nb][0] + bv0, v1 = p[nb][1] + bv1;
                float v2 = p[nb][2] + bv0, v3 = p[nb][3] + bv1;
                Gc[IDX(row,   col  )] = f2tf32(0.5f*v0*(1.0f + erff(v0*0.7071067811865476f)));
                Gc[IDX(row,   col+1)] = f2tf32(0.5f*v1*(1.0f + erff(v1*0.7071067811865476f)));
                Gc[IDX(row+8, col  )] = f2tf32(0.5f*v2*(1.0f + erff(v2*0.7071067811865476f)));
                Gc[IDX(row+8, col+1)] = f2tf32(0.5f*v3*(1.0f + erff(v3*0.7071067811865476f)));
            }
        }
        __syncthreads();   // phase1 reads of Wt + Gc writes done
#pragma unroll 4
        for (int i = tx; i < 4096; i += 256) {
            int r = i >> 6, c = i & 63;
            Wt[IDX(r,c)] = f2tf32(W2[(ch*64 + r)*64 + c]);
        }
        __syncthreads();
        // phase2: acc += Gc @ W2c
#pragma unroll
        for (int k8 = 0; k8 < 8; k8++) {
            int kk = k8 * 8;
            int ar = mrow + (lane >> 2), ac = kk + (lane & 3);
            unsigned a0 = Gc[IDX(ar,   ac)];
            unsigned a1 = Gc[IDX(ar+8, ac)];
            unsigned a2 = Gc[IDX(ar,   ac+4)];
            unsigned a3 = Gc[IDX(ar+8, ac+4)];
#pragma unroll
            for (int nb = 0; nb < 4; nb++) {
                int n0 = ncol + nb*8;
                unsigned b0 = Wt[IDX(kk + (lane & 3),     n0 + (lane >> 2))];
                unsigned b1 = Wt[IDX(kk + (lane & 3) + 4, n0 + (lane >> 2))];
                mma_tf32(acc[nb], a0, a1, a2, a3, b0, b1);
            }
        }
    }
    __syncthreads();
    // y = acc + b2 + residual(h2); ys aliases Wt
    float* ys = (float*)Wt;
    {
        int row = mrow + (lane >> 2);
#pragma unroll
        for (int nb = 0; nb < 4; nb++) {
            int col = ncol + nb*8 + 2*(lane & 3);
            ys[IDX(row,   col  )] = acc[nb][0] + b2[col]   + Asm[IDX(row,   col)];
            ys[IDX(row,   col+1)] = acc[nb][1] + b2[col+1] + Asm[IDX(row,   col+1)];
            ys[IDX(row+8, col  )] = acc[nb][2] + b2[col]   + Asm[IDX(row+8, col)];
            ys[IDX(row+8, col+1)] = acc[nb][3] + b2[col+1] + Asm[IDX(row+8, col+1)];
        }
    }
    __syncthreads();
    float* part_s = (float*)Gc;
    float* part_q = (float*)Gc + 256;
    float* mu     = (float*)Gc + 512;
    float* rs     = (float*)Gc + 576;
    {
        int row = tx >> 2, seg = tx & 3;
        float s = 0.f, q = 0.f;
#pragma unroll
        for (int cc = 0; cc < 16; cc++) {
            float v = ys[IDX(row, seg*16 + cc)];
            s += v; q += v*v;
        }
        part_s[tx] = s; part_q[tx] = q;
    }
    __syncthreads();
    if (tx < 64) {
        float S = part_s[tx*4] + part_s[tx*4+1] + part_s[tx*4+2] + part_s[tx*4+3];
        float Q = part_q[tx*4] + part_q[tx*4+1] + part_q[tx*4+2] + part_q[tx*4+3];
        float m = S * (1.0f/64.f);
        float var = Q * (1.0f/64.f) - m*m;
        mu[tx] = m; rs[tx] = rsqrtf(var + EPS);
    }
    __syncthreads();
#pragma unroll 4
    for (int i = tx; i < 4096; i += 256) {
        int r = i >> 6, c = i & 63;
        out[(mbase + r)*64 + c] = (ys[IDX(r,c)] - mu[r]) * rs[r] * g[c] + bb[c];
    }
}

// ---------------- launch ----------------
extern "C" void kernel_launch(void* const* d_in, const int* in_sizes, int n_in,
                              void* d_out, int out_size) {
    const float* x   = (const float*)d_in[0];
    const float* adj = (const float*)d_in[1];
    const float* Wq  = (const float*)d_in[2];
    const float* bq  = (const float*)d_in[3];
    const float* Wk  = (const float*)d_in[4];
    const float* bk  = (const float*)d_in[5];
    const float* Wv  = (const float*)d_in[6];
    const float* bv  = (const float*)d_in[7];
    const float* Wo  = (const float*)d_in[8];
    const float* bo  = (const float*)d_in[9];
    const float* gcW = (const float*)d_in[10];
    const float* gcb = (const float*)d_in[11];
    const float* W1  = (const float*)d_in[12];
    const float* b1  = (const float*)d_in[13];
    const float* W2  = (const float*)d_in[14];
    const float* b2  = (const float*)d_in[15];
    const float* g_t = (const float*)d_in[16];
    const float* b_t = (const float*)d_in[17];
    const float* g_g = (const float*)d_in[18];
    const float* b_g = (const float*)d_in[19];
    const float* g_f = (const float*)d_in[20];
    const float* b_f = (const float*)d_in[21];
    float* out = (float*)d_out;

    deg_kernel<<<Ndim, 256>>>(adj);
    ahat_kernel<<<Ndim, Ndim>>>(adj);

    qkv_gemm<<<MTOK/64, 256>>>(x, Wq, bq, Wk, bk, Wv, bv);

    attn_kernel<<<Bdim*Ndim, 256>>>();

    oproj_ln<<<MTOK/64, 256>>>(x, Wo, bo, g_t, b_t);

    {
        dim3 grid(8, Bdim*Tdim);
        graph_gemm_tf32<<<grid, 256>>>(0);
        graph_gemm_tf32<<<grid, 256>>>(1);
    }
    gcomb_ln<<<MTOK/64, 256>>>(gcW, gcb, g_g, b_g);

    ffn_ln<<<MTOK/64, 256>>>(W1, b1, W2, b2, g_f, b_f, out);
}

// round 9
// speedup vs baseline: 2.5431x; 1.1026x over previous
#include <cuda_runtime.h>
#include <cuda_bf16.h>
#include <math.h>

#define Bdim 16
#define Tdim 24
#define Ndim 512
#define Ddim 64
#define Hdim 4
#define HD   16
#define Fdim 256
#define MTOK (Bdim*Tdim*Ndim)   // 196608
#define EPS  1e-5f

// XOR-quad swizzle for stride-64 fp32/tf32 smem tiles
#define IDX(r,c) (((r)<<6) | (((c)&3) | (((((c)>>2) ^ ((r)&7))&15) << 2)))

// ---------------- scratch (device-only references) ----------------
// q/k/v live in [B, N, T, D] layout; everything else token-major [B, T, N, D].
__device__ float d_q[MTOK*Ddim];
__device__ float d_k[MTOK*Ddim];
__device__ float d_v[MTOK*Ddim];
__device__ float d_att[MTOK*Ddim];
__device__ float d_h[MTOK*Ddim];
__device__ float d_p1[MTOK*Ddim];
__device__ float d_p2[MTOK*Ddim];
__device__ float d_h2[MTOK*Ddim];
__device__ float d_Ahat[Ndim*Ndim];
__device__ float d_dinv[Ndim];

__device__ __forceinline__ unsigned f2tf32(float x) {
    unsigned r;
    asm("cvt.rna.tf32.f32 %0, %1;" : "=r"(r) : "f"(x));
    return r;
}

__device__ __forceinline__ void mma_tf32(float c[4], unsigned a0, unsigned a1,
                                         unsigned a2, unsigned a3,
                                         unsigned b0, unsigned b1) {
    asm volatile(
        "mma.sync.aligned.m16n8k8.row.col.f32.tf32.tf32.f32 "
        "{%0,%1,%2,%3}, {%4,%5,%6,%7}, {%8,%9}, {%0,%1,%2,%3};"
        : "+f"(c[0]), "+f"(c[1]), "+f"(c[2]), "+f"(c[3])
        : "r"(a0), "r"(a1), "r"(a2), "r"(a3), "r"(b0), "r"(b1));
}

// 64x64x64 MMA tile: As [m][k], Bs [k][n], both tf32 swizzled. 8 warps.
__device__ __forceinline__ void mma_64x64(float acc[4][4], const unsigned* As,
                                          const unsigned* Bs, int mrow, int ncol, int lane) {
#pragma unroll
    for (int k8 = 0; k8 < 8; k8++) {
        int kk = k8 * 8;
        int ar = mrow + (lane >> 2), ac = kk + (lane & 3);
        unsigned a0 = As[IDX(ar,   ac)];
        unsigned a1 = As[IDX(ar+8, ac)];
        unsigned a2 = As[IDX(ar,   ac+4)];
        unsigned a3 = As[IDX(ar+8, ac+4)];
#pragma unroll
        for (int nb = 0; nb < 4; nb++) {
            int n0 = ncol + nb*8;
            unsigned b0 = Bs[IDX(kk + (lane & 3),     n0 + (lane >> 2))];
            unsigned b1 = Bs[IDX(kk + (lane & 3) + 4, n0 + (lane >> 2))];
            mma_tf32(acc[nb], a0, a1, a2, a3, b0, b1);
        }
    }
}

// ---------------- degree / Ahat ----------------
__global__ void deg_kernel(const float* __restrict__ adj) {
    int m = blockIdx.x, tx = threadIdx.x;
    float s = 0.f;
    for (int n = tx; n < Ndim; n += 256) s += adj[m*Ndim + n];
    __shared__ float red[256];
    red[tx] = s; __syncthreads();
#pragma unroll
    for (int st = 128; st > 0; st >>= 1) {
        if (tx < st) red[tx] += red[tx + st];
        __syncthreads();
    }
    if (tx == 0) d_dinv[m] = rsqrtf(fmaxf(red[0] + 1.0f, 1e-12f));
}

__global__ void ahat_kernel(const float* __restrict__ adj) {
    int m = blockIdx.x, n = threadIdx.x;
    float a = adj[m*Ndim + n] + (m == n ? 1.0f : 0.0f);
    d_Ahat[m*Ndim + n] = d_dinv[m] * a * d_dinv[n];
}

// ---------------- fused QKV (tf32 mma), writes [B,N,T,D] ----------------
__global__ void qkv_gemm(const float* __restrict__ x,
                         const float* __restrict__ Wq, const float* __restrict__ bq,
                         const float* __restrict__ Wk, const float* __restrict__ bk,
                         const float* __restrict__ Wv, const float* __restrict__ bv) {
    __shared__ unsigned As[4096];
    __shared__ unsigned Wt[4096];
    int tx = threadIdx.x;
    int wid = tx >> 5, lane = tx & 31;
    int mrow = (wid >> 1) * 16, ncol = (wid & 1) * 32;
    size_t mbase = (size_t)blockIdx.x * 64;
    // 64 consecutive tokens share (b, t); n = nbase + row (N=512 divisible by 64)
    int b = (int)(mbase / (Tdim*Ndim));
    int rem = (int)(mbase % (Tdim*Ndim));
    int t = rem / Ndim, nbase = rem % Ndim;
#pragma unroll 4
    for (int i = tx; i < 4096; i += 256) {
        int r = i >> 6, c = i & 63;
        As[IDX(r,c)] = f2tf32(x[(mbase + r)*64 + c]);
    }
    const float* Wm[3] = {Wq, Wk, Wv};
    const float* bm[3] = {bq, bk, bv};
    float* Om[3] = {d_q, d_k, d_v};
#pragma unroll
    for (int m = 0; m < 3; m++) {
        __syncthreads();
        const float* W = Wm[m];
#pragma unroll 4
        for (int i = tx; i < 4096; i += 256) {
            int r = i >> 6, c = i & 63;
            Wt[IDX(r,c)] = f2tf32(W[r*64 + c]);
        }
        __syncthreads();
        float acc[4][4] = {};
        mma_64x64(acc, As, Wt, mrow, ncol, lane);
        float* O = Om[m];
        const float* bias = bm[m];
        int row = mrow + (lane >> 2);
#pragma unroll
        for (int nb = 0; nb < 4; nb++) {
            int col = ncol + nb*8 + 2*(lane & 3);
            float b0v = bias[col], b1v = bias[col+1];
            size_t o0 = ((size_t)(b*Ndim + nbase + row    )*Tdim + t)*64 + col;
            size_t o1 = ((size_t)(b*Ndim + nbase + row + 8)*Tdim + t)*64 + col;
            *(float2*)&O[o0] = make_float2(acc[nb][0] + b0v, acc[nb][1] + b1v);
            *(float2*)&O[o1] = make_float2(acc[nb][2] + b0v, acc[nb][3] + b1v);
        }
    }
}

// ---------------- temporal attention: contiguous reads from [B,N,T,D] ----------------
__global__ void attn_kernel() {
    int bn = blockIdx.x;
    int b = bn / Ndim, n = bn % Ndim;
    size_t base = (size_t)bn * Tdim * Ddim;   // q/k/v contiguous chunk for this (b,n)
    __shared__ __align__(16) float qs[Tdim][Ddim];
    __shared__ float kst[Ddim][25];
    __shared__ __align__(16) float vs[Tdim][Ddim];
    __shared__ float sc[Hdim][Tdim][Tdim];
    int tx = threadIdx.x;  // 256
    // contiguous float4 loads: 384 float4s per tensor
    {
        const float4* q4 = (const float4*)(d_q + base);
        const float4* k4 = (const float4*)(d_k + base);
        const float4* v4 = (const float4*)(d_v + base);
        float4* qs4 = (float4*)&qs[0][0];
        float4* vs4 = (float4*)&vs[0][0];
        for (int i = tx; i < Tdim*16; i += 256) {
            qs4[i] = q4[i];
            vs4[i] = v4[i];
            float4 kv = k4[i];
            int t = i >> 4, d = (i & 15) * 4;
            kst[d+0][t] = kv.x; kst[d+1][t] = kv.y; kst[d+2][t] = kv.z; kst[d+3][t] = kv.w;
        }
    }
    __syncthreads();
    for (int i = tx; i < Hdim*Tdim*Tdim; i += 256) {
        int h = i / (Tdim*Tdim), r = i % (Tdim*Tdim);
        int tq = r / Tdim, tk = r % Tdim;
        float s = 0.f;
#pragma unroll
        for (int d = 0; d < HD; d++) s += qs[tq][h*HD + d] * kst[h*HD + d][tk];
        sc[h][tq][tk] = s * 0.25f;
    }
    __syncthreads();
    if (tx < Hdim*Tdim) {
        int h = tx / Tdim, tq = tx % Tdim;
        float m = -1e30f;
#pragma unroll
        for (int tk = 0; tk < Tdim; tk++) m = fmaxf(m, sc[h][tq][tk]);
        float sum = 0.f;
#pragma unroll
        for (int tk = 0; tk < Tdim; tk++) {
            float e = __expf(sc[h][tq][tk] - m);
            sc[h][tq][tk] = e; sum += e;
        }
        float inv = 1.0f / sum;
#pragma unroll
        for (int tk = 0; tk < Tdim; tk++) sc[h][tq][tk] *= inv;
    }
    __syncthreads();
    // V-apply; write d_att token-major (scattered 16B writes, fire-and-forget)
    const float4* vs4 = (const float4*)&vs[0][0];
    float4* att4 = (float4*)d_att;
    for (int i = tx; i < Tdim*16; i += 256) {
        int tq = i >> 4, d4 = i & 15;
        int h = d4 >> 2;
        float4 o = make_float4(0.f, 0.f, 0.f, 0.f);
#pragma unroll
        for (int tk = 0; tk < Tdim; tk++) {
            float s = sc[h][tq][tk];
            float4 vv = vs4[tk*16 + d4];
            o.x += s*vv.x; o.y += s*vv.y; o.z += s*vv.z; o.w += s*vv.w;
        }
        att4[(((size_t)b*Tdim + tq)*Ndim + n)*16 + d4] = o;
    }
}

// ---------------- O-proj (tf32 mma) + residual + LN -> d_h ----------------
__global__ void oproj_ln(const float* __restrict__ x,
                         const float* __restrict__ Wo, const float* __restrict__ bo,
                         const float* __restrict__ g, const float* __restrict__ bb) {
    __shared__ unsigned As[4096];   // tf32 att tile; later aliased by ys (fp32)
    __shared__ unsigned Wt[4096];   // tf32 Wo; later LN scratch
    int tx = threadIdx.x;
    int wid = tx >> 5, lane = tx & 31;
    int mrow = (wid >> 1) * 16, ncol = (wid & 1) * 32;
    size_t mbase = (size_t)blockIdx.x * 64;
#pragma unroll 4
    for (int i = tx; i < 4096; i += 256) {
        int r = i >> 6, c = i & 63;
        As[IDX(r,c)] = f2tf32(d_att[(mbase + r)*64 + c]);
        Wt[IDX(r,c)] = f2tf32(Wo[r*64 + c]);
    }
    __syncthreads();
    float acc[4][4] = {};
    mma_64x64(acc, As, Wt, mrow, ncol, lane);
    __syncthreads();   // all reads of As done
    float* ys = (float*)As;
    {
        int row = mrow + (lane >> 2);
#pragma unroll
        for (int nb = 0; nb < 4; nb++) {
            int col = ncol + nb*8 + 2*(lane & 3);
            float2 x0 = *(const float2*)&x[(mbase + row    )*64 + col];
            float2 x1 = *(const float2*)&x[(mbase + row + 8)*64 + col];
            ys[IDX(row,   col  )] = acc[nb][0] + bo[col]   + x0.x;
            ys[IDX(row,   col+1)] = acc[nb][1] + bo[col+1] + x0.y;
            ys[IDX(row+8, col  )] = acc[nb][2] + bo[col]   + x1.x;
            ys[IDX(row+8, col+1)] = acc[nb][3] + bo[col+1] + x1.y;
        }
    }
    __syncthreads();
    float* part_s = (float*)Wt;
    float* part_q = (float*)Wt + 256;
    float* mu     = (float*)Wt + 512;
    float* rs     = (float*)Wt + 576;
    {
        int row = tx >> 2, seg = tx & 3;
        float s = 0.f, q = 0.f;
#pragma unroll
        for (int cc = 0; cc < 16; cc++) {
            float v = ys[IDX(row, seg*16 + cc)];
            s += v; q += v*v;
        }
        part_s[tx] = s; part_q[tx] = q;
    }
    __syncthreads();
    if (tx < 64) {
        float S = part_s[tx*4] + part_s[tx*4+1] + part_s[tx*4+2] + part_s[tx*4+3];
        float Q = part_q[tx*4] + part_q[tx*4+1] + part_q[tx*4+2] + part_q[tx*4+3];
        float m = S * (1.0f/64.f);
        float var = Q * (1.0f/64.f) - m*m;
        mu[tx] = m; rs[tx] = rsqrtf(var + EPS);
    }
    __syncthreads();
#pragma unroll 4
    for (int i = tx; i < 4096; i += 256) {
        int r = i >> 6, c = i & 63;
        d_h[(mbase + r)*64 + c] = (ys[IDX(r,c)] - mu[r]) * rs[r] * g[c] + bb[c];
    }
}

// ---------------- graph GEMM via tf32 mma (unchanged from R5) ----------------
__global__ void graph_gemm_tf32(int stage) {
    const float* __restrict__ Hin = stage ? (const float*)d_p1 : (const float*)d_h;
    float* __restrict__ Hout      = stage ? d_p2 : d_p1;
    __shared__ unsigned As[4096];
    __shared__ unsigned Bs[4096];
    int tx = threadIdx.x;
    int wid = tx >> 5, lane = tx & 31;
    int mrow = (wid >> 1) * 16, ncol = (wid & 1) * 32;
    int mbase = blockIdx.x * 64;
    size_t hbase = (size_t)blockIdx.y * Ndim * Ddim;
    float acc[4][4] = {};
    for (int kt = 0; kt < 8; kt++) {
        __syncthreads();
#pragma unroll 4
        for (int i = tx; i < 4096; i += 256) {
            int r = i >> 6, c = i & 63;
            As[IDX(r,c)] = f2tf32(d_Ahat[(size_t)(mbase + r)*Ndim + kt*64 + c]);
            Bs[IDX(r,c)] = f2tf32(Hin[hbase + (size_t)(kt*64 + r)*64 + c]);
        }
        __syncthreads();
        mma_64x64(acc, As, Bs, mrow, ncol, lane);
    }
    int row = mbase + mrow + (lane >> 2);
#pragma unroll
    for (int nb = 0; nb < 4; nb++) {
        int col = ncol + nb*8 + 2*(lane & 3);
        *(float2*)&Hout[hbase + (size_t)row*64 + col]     = make_float2(acc[nb][0], acc[nb][1]);
        *(float2*)&Hout[hbase + (size_t)(row+8)*64 + col] = make_float2(acc[nb][2], acc[nb][3]);
    }
}

// ---------------- gc combine (3x tf32 mma) + residual + LN -> d_h2 ----------------
__global__ void gcomb_ln(const float* __restrict__ gcW, const float* __restrict__ gcb,
                         const float* __restrict__ g, const float* __restrict__ bb) {
    __shared__ unsigned In[4096];   // later ys
    __shared__ unsigned Ws[4096];   // later LN scratch
    int tx = threadIdx.x;
    int wid = tx >> 5, lane = tx & 31;
    int mrow = (wid >> 1) * 16, ncol = (wid & 1) * 32;
    size_t mbase = (size_t)blockIdx.x * 64;
    float acc[4][4] = {};
#pragma unroll
    for (int s = 0; s < 3; s++) {
        const float* Hin = (s == 0) ? (const float*)d_h : (s == 1) ? (const float*)d_p1 : (const float*)d_p2;
        __syncthreads();
#pragma unroll 4
        for (int i = tx; i < 4096; i += 256) {
            int r = i >> 6, c = i & 63;
            In[IDX(r,c)] = f2tf32(Hin[(mbase + r)*64 + c]);
            Ws[IDX(r,c)] = f2tf32(gcW[s*4096 + r*64 + c]);
        }
        __syncthreads();
        mma_64x64(acc, In, Ws, mrow, ncol, lane);
    }
    __syncthreads();
    float* ys = (float*)In;
    {
        int row = mrow + (lane >> 2);
#pragma unroll
        for (int nb = 0; nb < 4; nb++) {
            int col = ncol + nb*8 + 2*(lane & 3);
            float gb0 = gcb[col]   + gcb[64+col]   + gcb[128+col];
            float gb1 = gcb[col+1] + gcb[64+col+1] + gcb[128+col+1];
            float2 h0 = *(const float2*)&d_h[(mbase + row    )*64 + col];
            float2 h1 = *(const float2*)&d_h[(mbase + row + 8)*64 + col];
            ys[IDX(row,   col  )] = acc[nb][0] + gb0 + h0.x;
            ys[IDX(row,   col+1)] = acc[nb][1] + gb1 + h0.y;
            ys[IDX(row+8, col  )] = acc[nb][2] + gb0 + h1.x;
            ys[IDX(row+8, col+1)] = acc[nb][3] + gb1 + h1.y;
        }
    }
    __syncthreads();
    float* part_s = (float*)Ws;
    float* part_q = (float*)Ws + 256;
    float* mu     = (float*)Ws + 512;
    float* rs     = (float*)Ws + 576;
    {
        int row = tx >> 2, seg = tx & 3;
        float s = 0.f, q = 0.f;
#pragma unroll
        for (int cc = 0; cc < 16; cc++) {
            float v = ys[IDX(row, seg*16 + cc)];
            s += v; q += v*v;
        }
        part_s[tx] = s; part_q[tx] = q;
    }
    __syncthreads();
    if (tx < 64) {
        float S = part_s[tx*4] + part_s[tx*4+1] + part_s[tx*4+2] + part_s[tx*4+3];
        float Q = part_q[tx*4] + part_q[tx*4+1] + part_q[tx*4+2] + part_q[tx*4+3];
        float m = S * (1.0f/64.f);
        float var = Q * (1.0f/64.f) - m*m;
        mu[tx] = m; rs[tx] = rsqrtf(var + EPS);
    }
    __syncthreads();
#pragma unroll 4
    for (int i = tx; i < 4096; i += 256) {
        int r = i >> 6, c = i & 63;
        d_h2[(mbase + r)*64 + c] = (ys[IDX(r,c)] - mu[r]) * rs[r] * g[c] + bb[c];
    }
}

// ---------------- FFN via tf32 mma + residual + LN (unchanged from R5) ----------------
__global__ void ffn_ln(const float* __restrict__ W1, const float* __restrict__ b1,
                       const float* __restrict__ W2, const float* __restrict__ b2,
                       const float* __restrict__ g, const float* __restrict__ bb,
                       float* __restrict__ out) {
    __shared__ float    Asm[4096];
    __shared__ unsigned Wt[4096];
    __shared__ unsigned Gc[4096];
    int tx = threadIdx.x;
    int wid = tx >> 5, lane = tx & 31;
    int mrow = (wid >> 1) * 16, ncol = (wid & 1) * 32;
    size_t mbase = (size_t)blockIdx.x * 64;
#pragma unroll 4
    for (int i = tx; i < 4096; i += 256) {
        int r = i >> 6, c = i & 63;
        Asm[IDX(r,c)] = d_h2[(mbase + r)*64 + c];
    }
    float acc[4][4] = {};
#pragma unroll
    for (int ch = 0; ch < 4; ch++) {
        __syncthreads();
#pragma unroll 4
        for (int i = tx; i < 4096; i += 256) {
            int r = i >> 6, c = i & 63;
            Wt[IDX(r,c)] = f2tf32(W1[r*Fdim + ch*64 + c]);
        }
        __syncthreads();
        float p[4][4] = {};
#pragma unroll
        for (int k8 = 0; k8 < 8; k8++) {
            int kk = k8 * 8;
            int ar = mrow + (lane >> 2), ac = kk + (lane & 3);
            unsigned a0 = f2tf32(Asm[IDX(ar,   ac)]);
            unsigned a1 = f2tf32(Asm[IDX(ar+8, ac)]);
            unsigned a2 = f2tf32(Asm[IDX(ar,   ac+4)]);
            unsigned a3 = f2tf32(Asm[IDX(ar+8, ac+4)]);
#pragma unroll
            for (int nb = 0; nb < 4; nb++) {
                int n0 = ncol + nb*8;
                unsigned b0 = Wt[IDX(kk + (lane & 3),     n0 + (lane >> 2))];
                unsigned b1 = Wt[IDX(kk + (lane & 3) + 4, n0 + (lane >> 2))];
                mma_tf32(p[nb], a0, a1, a2, a3, b0, b1);
            }
        }
        {
            int row = mrow + (lane >> 2);
#pragma unroll
            for (int nb = 0; nb < 4; nb++) {
                int col = ncol + nb*8 + 2*(lane & 3);
                float bv0 = b1[ch*64 + col], bv1 = b1[ch*64 + col + 1];
                float v0 = p[nb][0] + bv0, v1 = p[nb][1] + bv1;
                float v2 = p[nb][2] + bv0, v3 = p[nb][3] + bv1;
                Gc[IDX(row,   col  )] = f2tf32(0.5f*v0*(1.0f + erff(v0*0.7071067811865476f)));
                Gc[IDX(row,   col+1)] = f2tf32(0.5f*v1*(1.0f + erff(v1*0.7071067811865476f)));
                Gc[IDX(row+8, col  )] = f2tf32(0.5f*v2*(1.0f + erff(v2*0.7071067811865476f)));
                Gc[IDX(row+8, col+1)] = f2tf32(0.5f*v3*(1.0f + erff(v3*0.7071067811865476f)));
            }
        }
        __syncthreads();
#pragma unroll 4
        for (int i = tx; i < 4096; i += 256) {
            int r = i >> 6, c = i & 63;
            Wt[IDX(r,c)] = f2tf32(W2[(ch*64 + r)*64 + c]);
        }
        __syncthreads();
        mma_64x64(acc, Gc, Wt, mrow, ncol, lane);
    }
    __syncthreads();
    float* ys = (float*)Wt;
    {
        int row = mrow + (lane >> 2);
#pragma unroll
        for (int nb = 0; nb < 4; nb++) {
            int col = ncol + nb*8 + 2*(lane & 3);
            ys[IDX(row,   col  )] = acc[nb][0] + b2[col]   + Asm[IDX(row,   col)];
            ys[IDX(row,   col+1)] = acc[nb][1] + b2[col+1] + Asm[IDX(row,   col+1)];
            ys[IDX(row+8, col  )] = acc[nb][2] + b2[col]   + Asm[IDX(row+8, col)];
            ys[IDX(row+8, col+1)] = acc[nb][3] + b2[col+1] + Asm[IDX(row+8, col+1)];
        }
    }
    __syncthreads();
    float* part_s = (float*)Gc;
    float* part_q = (float*)Gc + 256;
    float* mu     = (float*)Gc + 512;
    float* rs     = (float*)Gc + 576;
    {
        int row = tx >> 2, seg = tx & 3;
        float s = 0.f, q = 0.f;
#pragma unroll
        for (int cc = 0; cc < 16; cc++) {
            float v = ys[IDX(row, seg*16 + cc)];
            s += v; q += v*v;
        }
        part_s[tx] = s; part_q[tx] = q;
    }
    __syncthreads();
    if (tx < 64) {
        float S = part_s[tx*4] + part_s[tx*4+1] + part_s[tx*4+2] + part_s[tx*4+3];
        float Q = part_q[tx*4] + part_q[tx*4+1] + part_q[tx*4+2] + part_q[tx*4+3];
        float m = S * (1.0f/64.f);
        float var = Q * (1.0f/64.f) - m*m;
        mu[tx] = m; rs[tx] = rsqrtf(var + EPS);
    }
    __syncthreads();
#pragma unroll 4
    for (int i = tx; i < 4096; i += 256) {
        int r = i >> 6, c = i & 63;
        out[(mbase + r)*64 + c] = (ys[IDX(r,c)] - mu[r]) * rs[r] * g[c] + bb[c];
    }
}

// ---------------- launch ----------------
extern "C" void kernel_launch(void* const* d_in, const int* in_sizes, int n_in,
                              void* d_out, int out_size) {
    const float* x   = (const float*)d_in[0];
    const float* adj = (const float*)d_in[1];
    const float* Wq  = (const float*)d_in[2];
    const float* bq  = (const float*)d_in[3];
    const float* Wk  = (const float*)d_in[4];
    const float* bk  = (const float*)d_in[5];
    const float* Wv  = (const float*)d_in[6];
    const float* bv  = (const float*)d_in[7];
    const float* Wo  = (const float*)d_in[8];
    const float* bo  = (const float*)d_in[9];
    const float* gcW = (const float*)d_in[10];
    const float* gcb = (const float*)d_in[11];
    const float* W1  = (const float*)d_in[12];
    const float* b1  = (const float*)d_in[13];
    const float* W2  = (const float*)d_in[14];
    const float* b2  = (const float*)d_in[15];
    const float* g_t = (const float*)d_in[16];
    const float* b_t = (const float*)d_in[17];
    const float* g_g = (const float*)d_in[18];
    const float* b_g = (const float*)d_in[19];
    const float* g_f = (const float*)d_in[20];
    const float* b_f = (const float*)d_in[21];
    float* out = (float*)d_out;

    deg_kernel<<<Ndim, 256>>>(adj);
    ahat_kernel<<<Ndim, Ndim>>>(adj);

    qkv_gemm<<<MTOK/64, 256>>>(x, Wq, bq, Wk, bk, Wv, bv);

    attn_kernel<<<Bdim*Ndim, 256>>>();

    oproj_ln<<<MTOK/64, 256>>>(x, Wo, bo, g_t, b_t);

    {
        dim3 grid(8, Bdim*Tdim);
        graph_gemm_tf32<<<grid, 256>>>(0);
        graph_gemm_tf32<<<grid, 256>>>(1);
    }
    gcomb_ln<<<MTOK/64, 256>>>(gcW, gcb, g_g, b_g);

    ffn_ln<<<MTOK/64, 256>>>(W1, b1, W2, b2, g_f, b_f, out);
}